// round 10
// baseline (speedup 1.0000x reference)
#include <cuda_runtime.h>

// BoundaryBCELoss: 5x clamped plus-dilation of two masks + BCE vs target, mean-reduced.
// Round 10: overhead/latency cuts on the R9 two-kernel split.
//  (1) zero_out kernel removed: device accumulator + completion counter; the LAST
//      fallback block writes d_out and resets the statics (clean state every call).
//  (2) target rows L2-prefetched during staging (2 lanes/warp/row) so the
//      post-certificate target loads hit L2 instead of DRAM -> shorter tail.
//  Fast path unchanged: halo-2 register-resident tile, 2 iterations, certificate
//  (all inner cells bitwise 1.0f -> h5=o5=1 on tile -> BCE = -100*sum(1-t)),
//  fallback = full halo-5 5-iteration kernel for flagged blocks only.

#define W_IMG 384
#define H_IMG 384
#define N_IMG 64
#define TILE 48
#define NBLK 4096            // 8*8*64

// ---- fast kernel (A) geometry: halo 2 ----
#define A_HALO 2
#define A_LDIM 52            // TILE + 4
#define A_NP 26              // column pairs
#define A_RMAX 7             // warps 0-3: 7 rows, warps 4-7: 6 rows

// ---- fallback kernel (B) geometry: halo 5 (x-halo 6 for 8B alignment) ----
#define B_HALO_Y 5
#define B_HALO_X 6
#define B_LDIM_Y 58
#define B_LDIM_X 60
#define B_NP 30
#define B_RMAX 8             // warps 0,1: 8 rows, warps 2-7: 7 rows

#define NW 8
#define NTHREADS 256

typedef unsigned long long u64;
#define ONE2 0x3F8000003F800000ULL

#define ADD_F32X2(o, a, b) \
    asm("add.rn.f32x2 %0, %1, %2;" : "=l"(o) : "l"(a), "l"(b))
#define PACK2(o, lo, hi) \
    asm("mov.b64 %0, {%1, %2};" : "=l"(o) : "f"(lo), "f"(hi))
#define UNPACK2(lo, hi, in) \
    asm("mov.b64 {%0, %1}, %2;" : "=f"(lo), "=f"(hi) : "l"(in))

__device__ int   g_flags[NBLK];
__device__ float g_accum = 0.0f;     // reset by the final fallback block each call
__device__ int   g_done  = 0;        // ditto

// ============================ Kernel A: fast path ============================
__global__ __launch_bounds__(NTHREADS) void bce_fast_kernel(
    const float* __restrict__ hand,
    const float* __restrict__ obj,
    const float* __restrict__ target)
{
    __shared__ __align__(16) u64 xbuf[2][2][NW][A_NP][2];
    __shared__ float red[NW];

    const int n   = blockIdx.z;
    const int y0  = blockIdx.y * TILE - A_HALO;
    const int x0  = blockIdx.x * TILE - A_HALO;          // even
    const int tid = threadIdx.x;
    const int w   = tid >> 5;
    const int pl  = tid & 31;
    const int bid = (blockIdx.z * gridDim.y + blockIdx.y) * gridDim.x + blockIdx.x;

    // Row bands over 52 rows: warps 0-3 -> 7 rows; warps 4-7 -> 6 rows.
    const int r_lo = (w < 4) ? 7 * w : 6 * w + 4;
    const int R    = (w < 4) ? 7 : 6;

    const int  gx       = x0 + 2 * pl;
    const bool lane_act = (pl < A_NP);
    const bool col_in   = lane_act && ((unsigned)gx < W_IMG);
    const bool interior = (x0 >= 0) && (y0 >= 0) &&
                          (x0 + A_LDIM <= W_IMG) && (y0 + A_LDIM <= H_IMG);

    const size_t img = (size_t)n * H_IMG * W_IMG;
    const float* hb = hand + img;
    const float* ob = obj + img;
    const float* tb = target + img;

    // ---- Stage band rows into registers; prefetch target rows to L2 ----
    u64 ra[A_RMAX], rb[A_RMAX];
    #pragma unroll
    for (int i = 0; i < A_RMAX; i++) { ra[i] = 0; rb[i] = 0; }

    #pragma unroll
    for (int i = 0; i < A_RMAX; i++) {
        if (i < R) {
            const int rl = r_lo + i;
            const int gy = y0 + rl;
            if (col_in && (unsigned)gy < H_IMG) {
                const float2 hh = *(const float2*)(hb + gy * W_IMG + gx);
                const float2 oo = *(const float2*)(ob + gy * W_IMG + gx);
                PACK2(ra[i], hh.x, oo.x);
                PACK2(rb[i], hh.y, oo.y);
            }
            // Warm L2 with the target row this warp will read post-certificate.
            // Lanes 1 and 17 cover the 2-3 cache lines of the inner row span.
            if (((pl & 15) == 1) && rl >= A_HALO && rl < A_HALO + TILE)
                asm volatile("prefetch.global.L2 [%0];"
                             :: "l"(tb + (y0 + rl) * W_IMG + gx));
        }
    }

    // ---- 2 dilation iterations (with halo 2 the inner tile is EXACT h2/o2) ----
    #pragma unroll
    for (int k = 0; k < 2; k++) {
        const int p = k;

        if (lane_act) {
            const u64 ba = (R == 7) ? ra[6] : ra[5];   // constant-index select!
            const u64 bb = (R == 7) ? rb[6] : rb[5];
            *(ulonglong2*)&xbuf[p][0][w][pl][0] = make_ulonglong2(ra[0], rb[0]);
            *(ulonglong2*)&xbuf[p][1][w][pl][0] = make_ulonglong2(ba, bb);
        }
        __syncthreads();

        u64 pa = 0, pb = 0, na = 0, nb = 0;
        if (lane_act && w > 0) {
            ulonglong2 v = *(ulonglong2*)&xbuf[p][1][w - 1][pl][0];
            pa = v.x; pb = v.y;
        }
        if (lane_act && w < NW - 1) {
            ulonglong2 v = *(ulonglong2*)&xbuf[p][0][w + 1][pl][0];
            na = v.x; nb = v.y;
        }

        #pragma unroll
        for (int i = 0; i < A_RMAX; i++) {
            if (i < R) {
                const u64 ca = ra[i], cb = rb[i];
                u64 xa = na, xb = nb;
                if (i + 1 < A_RMAX) {
                    if (i + 1 < R) { xa = ra[i + 1]; xb = rb[i + 1]; }
                }
                const u64 lf = __shfl_up_sync(0xffffffffu, cb, 1);
                const u64 rt = __shfl_down_sync(0xffffffffu, ca, 1);

                u64 t, s0, s1;
                ADD_F32X2(t, ca, cb);
                ADD_F32X2(s0, t, lf);
                ADD_F32X2(s0, s0, pa);
                ADD_F32X2(s0, s0, xa);
                ADD_F32X2(s1, t, rt);
                ADD_F32X2(s1, s1, pb);
                ADD_F32X2(s1, s1, xb);

                float a0, a1, b0, b1;
                UNPACK2(a0, a1, s0);
                UNPACK2(b0, b1, s1);
                a0 = fminf(a0, 1.0f); a1 = fminf(a1, 1.0f);
                b0 = fminf(b0, 1.0f); b1 = fminf(b1, 1.0f);

                if (!interior) {
                    const bool rin = (unsigned)(y0 + r_lo + i) < H_IMG;
                    const bool in  = rin && col_in;
                    a0 = in ? a0 : 0.0f;  a1 = in ? a1 : 0.0f;
                    b0 = in ? b0 : 0.0f;  b1 = in ? b1 : 0.0f;
                }

                pa = ca; pb = cb;
                PACK2(ra[i], a0, a1);
                PACK2(rb[i], b0, b1);
            }
        }
        // one sync per iter: next iteration stores to the other parity slot
    }

    // ---- Certificate: all inner-tile cells (exact h2/o2, always in-image)
    //      bitwise {1.0f,1.0f} => true h5=o5=1 on the whole inner tile ----
    bool ok = true;
    if (pl >= 1 && pl <= 24) {                   // cols local [2,50)
        #pragma unroll
        for (int i = 0; i < A_RMAX; i++) {
            if (i < R) {
                const int rl = r_lo + i;
                if (rl >= A_HALO && rl < A_HALO + TILE)
                    ok = ok && (ra[i] == ONE2) && (rb[i] == ONE2);
            }
        }
    }
    const bool pass = __syncthreads_and(ok);

    if (tid == 0) g_flags[bid] = pass ? 0 : 1;
    if (!pass) return;                           // fallback kernel owns this block

    // ---- BCE with p==1 everywhere: contrib = -100*(1-t)  (target now in L2) ----
    float ts = 0.0f;
    int cells = 0;
    if (pl >= 1 && pl <= 24) {
        #pragma unroll
        for (int i = 0; i < A_RMAX; i++) {
            if (i < R) {
                const int rl = r_lo + i;
                if (rl >= A_HALO && rl < A_HALO + TILE) {
                    const float2 t2 = *(const float2*)(tb + (y0 + rl) * W_IMG + gx);
                    ts += t2.x + t2.y;
                    cells += 2;
                }
            }
        }
    }
    float lsum = -100.0f * ((float)cells - ts);

    #pragma unroll
    for (int off = 16; off > 0; off >>= 1)
        lsum += __shfl_down_sync(0xffffffffu, lsum, off);

    if (pl == 0) red[w] = lsum;
    __syncthreads();

    if (tid < NW) {
        float v = red[tid];
        #pragma unroll
        for (int off = NW / 2; off > 0; off >>= 1)
            v += __shfl_down_sync((1u << NW) - 1u, v, off);
        if (tid == 0) atomicAdd(&g_accum, v);
    }
}

// ========================= Kernel B: rare fallback ==========================
__global__ __launch_bounds__(NTHREADS) void bce_fallback_kernel(
    const float* __restrict__ hand,
    const float* __restrict__ obj,
    const float* __restrict__ target,
    float* __restrict__ out)
{
    const int bid = (blockIdx.z * gridDim.y + blockIdx.y) * gridDim.x + blockIdx.x;
    const int tid = threadIdx.x;

    if (g_flags[bid] != 0) {       // block-uniform; rare path does the full work
        __shared__ __align__(16) u64 xbuf[2][2][NW][B_NP][2];
        __shared__ float red[NW];

        const int n   = blockIdx.z;
        const int y0  = blockIdx.y * TILE - B_HALO_Y;
        const int x0  = blockIdx.x * TILE - B_HALO_X;    // even
        const int w   = tid >> 5;
        const int pl  = tid & 31;

        const int r_lo = 7 * w + (w < 2 ? w : 2);
        const int R    = (w < 2) ? 8 : 7;

        const int  gx       = x0 + 2 * pl;
        const bool lane_act = (pl < B_NP);
        const bool col_in   = lane_act && ((unsigned)gx < W_IMG);
        const bool interior = (x0 >= 0) && (y0 >= 0) &&
                              (x0 + B_LDIM_X <= W_IMG) && (y0 + B_LDIM_Y <= H_IMG);

        const size_t img = (size_t)n * H_IMG * W_IMG;
        const float* hb = hand + img;
        const float* ob = obj + img;

        u64 ra[B_RMAX], rb[B_RMAX];
        #pragma unroll
        for (int i = 0; i < B_RMAX; i++) { ra[i] = 0; rb[i] = 0; }

        #pragma unroll
        for (int i = 0; i < B_RMAX; i++) {
            if (i < R) {
                const int gy = y0 + r_lo + i;
                if (col_in && (unsigned)gy < H_IMG) {
                    const float2 hh = *(const float2*)(hb + gy * W_IMG + gx);
                    const float2 oo = *(const float2*)(ob + gy * W_IMG + gx);
                    PACK2(ra[i], hh.x, oo.x);
                    PACK2(rb[i], hh.y, oo.y);
                }
            }
        }

        #pragma unroll 1
        for (int k = 0; k < 5; k++) {
            const int p = k & 1;

            if (lane_act) {
                const u64 ba = (R == 8) ? ra[7] : ra[6]; // constant-index select!
                const u64 bb = (R == 8) ? rb[7] : rb[6];
                *(ulonglong2*)&xbuf[p][0][w][pl][0] = make_ulonglong2(ra[0], rb[0]);
                *(ulonglong2*)&xbuf[p][1][w][pl][0] = make_ulonglong2(ba, bb);
            }
            __syncthreads();

            u64 pa = 0, pb = 0, na = 0, nb = 0;
            if (lane_act && w > 0) {
                ulonglong2 v = *(ulonglong2*)&xbuf[p][1][w - 1][pl][0];
                pa = v.x; pb = v.y;
            }
            if (lane_act && w < NW - 1) {
                ulonglong2 v = *(ulonglong2*)&xbuf[p][0][w + 1][pl][0];
                na = v.x; nb = v.y;
            }

            #pragma unroll
            for (int i = 0; i < B_RMAX; i++) {
                if (i < R) {
                    const u64 ca = ra[i], cb = rb[i];
                    u64 xa = na, xb = nb;
                    if (i + 1 < B_RMAX) {
                        if (i + 1 < R) { xa = ra[i + 1]; xb = rb[i + 1]; }
                    }
                    const u64 lf = __shfl_up_sync(0xffffffffu, cb, 1);
                    const u64 rt = __shfl_down_sync(0xffffffffu, ca, 1);

                    u64 t, s0, s1;
                    ADD_F32X2(t, ca, cb);
                    ADD_F32X2(s0, t, lf);
                    ADD_F32X2(s0, s0, pa);
                    ADD_F32X2(s0, s0, xa);
                    ADD_F32X2(s1, t, rt);
                    ADD_F32X2(s1, s1, pb);
                    ADD_F32X2(s1, s1, xb);

                    float a0, a1, b0, b1;
                    UNPACK2(a0, a1, s0);
                    UNPACK2(b0, b1, s1);
                    a0 = fminf(a0, 1.0f); a1 = fminf(a1, 1.0f);
                    b0 = fminf(b0, 1.0f); b1 = fminf(b1, 1.0f);

                    if (!interior) {
                        const bool rin = (unsigned)(y0 + r_lo + i) < H_IMG;
                        const bool in  = rin && col_in;
                        a0 = in ? a0 : 0.0f;  a1 = in ? a1 : 0.0f;
                        b0 = in ? b0 : 0.0f;  b1 = in ? b1 : 0.0f;
                    }

                    pa = ca; pb = cb;
                    PACK2(ra[i], a0, a1);
                    PACK2(rb[i], b0, b1);
                }
            }
        }

        // ---- Full BCE (inner cols local [6,54) <=> lanes 3..26; rows [5,53)) ----
        float lsum = 0.0f;
        if (pl >= 3 && pl <= 26) {
            const float* tb = target + img;
            #pragma unroll
            for (int i = 0; i < B_RMAX; i++) {
                if (i < R) {
                    const int rl = r_lo + i;
                    if (rl >= B_HALO_Y && rl < B_HALO_Y + TILE) {
                        const float2 t2 = *(const float2*)(tb + (y0 + rl) * W_IMG + gx);
                        float h0, o0, h1, o1;
                        UNPACK2(h0, o0, ra[i]);
                        UNPACK2(h1, o1, rb[i]);
                        const float p0 = h0 * o0;
                        const float p1 = h1 * o1;
                        float c0, c1;
                        if (p0 >= 1.0f) c0 = -100.0f * (1.0f - t2.x);
                        else {
                            float lp  = fmaxf(logf(p0), -100.0f);
                            float l1p = fmaxf(logf(1.0f - p0), -100.0f);
                            c0 = t2.x * lp + (1.0f - t2.x) * l1p;
                        }
                        if (p1 >= 1.0f) c1 = -100.0f * (1.0f - t2.y);
                        else {
                            float lp  = fmaxf(logf(p1), -100.0f);
                            float l1p = fmaxf(logf(1.0f - p1), -100.0f);
                            c1 = t2.y * lp + (1.0f - t2.y) * l1p;
                        }
                        lsum += c0 + c1;
                    }
                }
            }
        }

        #pragma unroll
        for (int off = 16; off > 0; off >>= 1)
            lsum += __shfl_down_sync(0xffffffffu, lsum, off);

        if (pl == 0) red[w] = lsum;
        __syncthreads();

        if (tid < NW) {
            float v = red[tid];
            #pragma unroll
            for (int off = NW / 2; off > 0; off >>= 1)
                v += __shfl_down_sync((1u << NW) - 1u, v, off);
            if (tid == 0) atomicAdd(&g_accum, v);
        }
    }

    // ---- Completion protocol: last block writes the loss and resets state ----
    // All fast-kernel accum adds are visible (kernel boundary). Each fallback
    // block orders its own accum add before its g_done add via __threadfence.
    if (tid == 0) {
        __threadfence();
        const int t = atomicAdd(&g_done, 1);
        if (t == NBLK - 1) {
            __threadfence();
            const float a = *((volatile float*)&g_accum);
            const float inv_total = 1.0f / ((float)N_IMG * H_IMG * W_IMG);
            *out = -a * inv_total;
            g_accum = 0.0f;      // clean state for the next call
            g_done  = 0;
            __threadfence();
        }
    }
}

extern "C" void kernel_launch(void* const* d_in, const int* in_sizes, int n_in,
                              void* d_out, int out_size)
{
    const float* hand   = (const float*)d_in[0];
    const float* obj    = (const float*)d_in[1];
    const float* target = (const float*)d_in[2];
    float* out = (float*)d_out;

    dim3 grid(W_IMG / TILE, H_IMG / TILE, N_IMG);    // 8 x 8 x 64 = 4096 blocks
    bce_fast_kernel<<<grid, NTHREADS>>>(hand, obj, target);
    bce_fallback_kernel<<<grid, NTHREADS>>>(hand, obj, target, out);
}

// round 11
// speedup vs baseline: 1.1651x; 1.1651x over previous
#include <cuda_runtime.h>

// BoundaryBCELoss: 5x clamped plus-dilation of two masks + BCE vs target, mean-reduced.
// Round 11: R10's regression was the completion protocol -- 4096 blocks serializing
// atomicAdd(&g_done) on one address (fallback kernel 2.9us -> 15.9us). Replaced with:
//  - failure QUEUE: failing fast-blocks push their bid (expected zero pushes);
//  - fallback kernel shrunk to 148 blocks (one wave) striding the queue, full halo-5
//    pipeline only per queue entry;
//  - completion counter among 148 blocks only; last block writes out and resets state.
// Fast kernel unchanged from R10 (halo-2 register tile, 2 iters, bitwise-1 certificate,
// target L2-prefetch during staging -- that part gained ~2us and is kept).

#define W_IMG 384
#define H_IMG 384
#define N_IMG 64
#define TILE 48
#define NBLK 4096            // fast grid: 8*8*64

// ---- fast kernel (A) geometry: halo 2 ----
#define A_HALO 2
#define A_LDIM 52            // TILE + 4
#define A_NP 26              // column pairs
#define A_RMAX 7             // warps 0-3: 7 rows, warps 4-7: 6 rows

// ---- fallback (B) geometry: halo 5 (x-halo 6 for 8B alignment) ----
#define B_HALO_Y 5
#define B_HALO_X 6
#define B_LDIM_Y 58
#define B_LDIM_X 60
#define B_NP 30
#define B_RMAX 8             // warps 0,1: 8 rows, warps 2-7: 7 rows

#define NW 8
#define NTHREADS 256
#define FB_GRID 148          // fallback grid: one wave

typedef unsigned long long u64;
#define ONE2 0x3F8000003F800000ULL

#define ADD_F32X2(o, a, b) \
    asm("add.rn.f32x2 %0, %1, %2;" : "=l"(o) : "l"(a), "l"(b))
#define PACK2(o, lo, hi) \
    asm("mov.b64 %0, {%1, %2};" : "=l"(o) : "f"(lo), "f"(hi))
#define UNPACK2(lo, hi, in) \
    asm("mov.b64 {%0, %1}, %2;" : "=f"(lo), "=f"(hi) : "l"(in))

__device__ int   g_list[NBLK];       // failed-bid queue
__device__ int   g_nfail = 0;        // queue length; reset by finalizer
__device__ float g_accum = 0.0f;     // loss accumulator; reset by finalizer
__device__ int   g_done  = 0;        // fallback completion counter; reset by finalizer

// ============================ Kernel A: fast path ============================
__global__ __launch_bounds__(NTHREADS) void bce_fast_kernel(
    const float* __restrict__ hand,
    const float* __restrict__ obj,
    const float* __restrict__ target)
{
    __shared__ __align__(16) u64 xbuf[2][2][NW][A_NP][2];
    __shared__ float red[NW];

    const int n   = blockIdx.z;
    const int y0  = blockIdx.y * TILE - A_HALO;
    const int x0  = blockIdx.x * TILE - A_HALO;          // even
    const int tid = threadIdx.x;
    const int w   = tid >> 5;
    const int pl  = tid & 31;
    const int bid = (blockIdx.z * gridDim.y + blockIdx.y) * gridDim.x + blockIdx.x;

    // Row bands over 52 rows: warps 0-3 -> 7 rows; warps 4-7 -> 6 rows.
    const int r_lo = (w < 4) ? 7 * w : 6 * w + 4;
    const int R    = (w < 4) ? 7 : 6;

    const int  gx       = x0 + 2 * pl;
    const bool lane_act = (pl < A_NP);
    const bool col_in   = lane_act && ((unsigned)gx < W_IMG);
    const bool interior = (x0 >= 0) && (y0 >= 0) &&
                          (x0 + A_LDIM <= W_IMG) && (y0 + A_LDIM <= H_IMG);

    const size_t img = (size_t)n * H_IMG * W_IMG;
    const float* hb = hand + img;
    const float* ob = obj + img;
    const float* tb = target + img;

    // ---- Stage band rows into registers; prefetch target rows to L2 ----
    u64 ra[A_RMAX], rb[A_RMAX];
    #pragma unroll
    for (int i = 0; i < A_RMAX; i++) { ra[i] = 0; rb[i] = 0; }

    #pragma unroll
    for (int i = 0; i < A_RMAX; i++) {
        if (i < R) {
            const int rl = r_lo + i;
            const int gy = y0 + rl;
            if (col_in && (unsigned)gy < H_IMG) {
                const float2 hh = *(const float2*)(hb + gy * W_IMG + gx);
                const float2 oo = *(const float2*)(ob + gy * W_IMG + gx);
                PACK2(ra[i], hh.x, oo.x);
                PACK2(rb[i], hh.y, oo.y);
            }
            // Warm L2 with the target row this warp reads post-certificate.
            if (((pl & 15) == 1) && rl >= A_HALO && rl < A_HALO + TILE)
                asm volatile("prefetch.global.L2 [%0];"
                             :: "l"(tb + (y0 + rl) * W_IMG + gx));
        }
    }

    // ---- 2 dilation iterations (halo-2 => inner tile is EXACT h2/o2) ----
    #pragma unroll
    for (int k = 0; k < 2; k++) {
        const int p = k;

        if (lane_act) {
            const u64 ba = (R == 7) ? ra[6] : ra[5];   // constant-index select!
            const u64 bb = (R == 7) ? rb[6] : rb[5];
            *(ulonglong2*)&xbuf[p][0][w][pl][0] = make_ulonglong2(ra[0], rb[0]);
            *(ulonglong2*)&xbuf[p][1][w][pl][0] = make_ulonglong2(ba, bb);
        }
        __syncthreads();

        u64 pa = 0, pb = 0, na = 0, nb = 0;
        if (lane_act && w > 0) {
            ulonglong2 v = *(ulonglong2*)&xbuf[p][1][w - 1][pl][0];
            pa = v.x; pb = v.y;
        }
        if (lane_act && w < NW - 1) {
            ulonglong2 v = *(ulonglong2*)&xbuf[p][0][w + 1][pl][0];
            na = v.x; nb = v.y;
        }

        #pragma unroll
        for (int i = 0; i < A_RMAX; i++) {
            if (i < R) {
                const u64 ca = ra[i], cb = rb[i];
                u64 xa = na, xb = nb;
                if (i + 1 < A_RMAX) {
                    if (i + 1 < R) { xa = ra[i + 1]; xb = rb[i + 1]; }
                }
                const u64 lf = __shfl_up_sync(0xffffffffu, cb, 1);
                const u64 rt = __shfl_down_sync(0xffffffffu, ca, 1);

                u64 t, s0, s1;
                ADD_F32X2(t, ca, cb);
                ADD_F32X2(s0, t, lf);
                ADD_F32X2(s0, s0, pa);
                ADD_F32X2(s0, s0, xa);
                ADD_F32X2(s1, t, rt);
                ADD_F32X2(s1, s1, pb);
                ADD_F32X2(s1, s1, xb);

                float a0, a1, b0, b1;
                UNPACK2(a0, a1, s0);
                UNPACK2(b0, b1, s1);
                a0 = fminf(a0, 1.0f); a1 = fminf(a1, 1.0f);
                b0 = fminf(b0, 1.0f); b1 = fminf(b1, 1.0f);

                if (!interior) {
                    const bool rin = (unsigned)(y0 + r_lo + i) < H_IMG;
                    const bool in  = rin && col_in;
                    a0 = in ? a0 : 0.0f;  a1 = in ? a1 : 0.0f;
                    b0 = in ? b0 : 0.0f;  b1 = in ? b1 : 0.0f;
                }

                pa = ca; pb = cb;
                PACK2(ra[i], a0, a1);
                PACK2(rb[i], b0, b1);
            }
        }
    }

    // ---- Certificate: all inner-tile cells bitwise {1,1} => h5=o5=1 on tile ----
    bool ok = true;
    if (pl >= 1 && pl <= 24) {                   // cols local [2,50)
        #pragma unroll
        for (int i = 0; i < A_RMAX; i++) {
            if (i < R) {
                const int rl = r_lo + i;
                if (rl >= A_HALO && rl < A_HALO + TILE)
                    ok = ok && (ra[i] == ONE2) && (rb[i] == ONE2);
            }
        }
    }
    const bool pass = __syncthreads_and(ok);

    if (!pass) {
        if (tid == 0) {
            const int pos = atomicAdd(&g_nfail, 1);
            g_list[pos] = bid;                   // fallback kernel handles this block
        }
        return;
    }

    // ---- BCE with p==1 everywhere: contrib = -100*(1-t)  (target in L2) ----
    float ts = 0.0f;
    int cells = 0;
    if (pl >= 1 && pl <= 24) {
        #pragma unroll
        for (int i = 0; i < A_RMAX; i++) {
            if (i < R) {
                const int rl = r_lo + i;
                if (rl >= A_HALO && rl < A_HALO + TILE) {
                    const float2 t2 = *(const float2*)(tb + (y0 + rl) * W_IMG + gx);
                    ts += t2.x + t2.y;
                    cells += 2;
                }
            }
        }
    }
    float lsum = -100.0f * ((float)cells - ts);

    #pragma unroll
    for (int off = 16; off > 0; off >>= 1)
        lsum += __shfl_down_sync(0xffffffffu, lsum, off);

    if (pl == 0) red[w] = lsum;
    __syncthreads();

    if (tid < NW) {
        float v = red[tid];
        #pragma unroll
        for (int off = NW / 2; off > 0; off >>= 1)
            v += __shfl_down_sync((1u << NW) - 1u, v, off);
        if (tid == 0) atomicAdd(&g_accum, v);
    }
}

// ============== Kernel B: queue-driven fallback + finalization ==============
__global__ __launch_bounds__(NTHREADS) void bce_fallback_kernel(
    const float* __restrict__ hand,
    const float* __restrict__ obj,
    const float* __restrict__ target,
    float* __restrict__ out)
{
    __shared__ __align__(16) u64 xbuf[2][2][NW][B_NP][2];
    __shared__ float red[NW];
    __shared__ int s_nfail;

    const int tid = threadIdx.x;
    const int w   = tid >> 5;
    const int pl  = tid & 31;

    if (tid == 0) s_nfail = *((volatile int*)&g_nfail);
    __syncthreads();
    const int nf = s_nfail;                      // block-uniform queue length

    for (int q = blockIdx.x; q < nf; q += gridDim.x) {
        const int bid = g_list[q];
        const int bx = bid & 7;
        const int by = (bid >> 3) & 7;
        const int n  = bid >> 6;

        const int y0 = by * TILE - B_HALO_Y;
        const int x0 = bx * TILE - B_HALO_X;     // even

        const int r_lo = 7 * w + (w < 2 ? w : 2);
        const int R    = (w < 2) ? 8 : 7;

        const int  gx       = x0 + 2 * pl;
        const bool lane_act = (pl < B_NP);
        const bool col_in   = lane_act && ((unsigned)gx < W_IMG);
        const bool interior = (x0 >= 0) && (y0 >= 0) &&
                              (x0 + B_LDIM_X <= W_IMG) && (y0 + B_LDIM_Y <= H_IMG);

        const size_t img = (size_t)n * H_IMG * W_IMG;
        const float* hb = hand + img;
        const float* ob = obj + img;

        u64 ra[B_RMAX], rb[B_RMAX];
        #pragma unroll
        for (int i = 0; i < B_RMAX; i++) { ra[i] = 0; rb[i] = 0; }

        #pragma unroll
        for (int i = 0; i < B_RMAX; i++) {
            if (i < R) {
                const int gy = y0 + r_lo + i;
                if (col_in && (unsigned)gy < H_IMG) {
                    const float2 hh = *(const float2*)(hb + gy * W_IMG + gx);
                    const float2 oo = *(const float2*)(ob + gy * W_IMG + gx);
                    PACK2(ra[i], hh.x, oo.x);
                    PACK2(rb[i], hh.y, oo.y);
                }
            }
        }

        #pragma unroll 1
        for (int k = 0; k < 5; k++) {
            const int p = k & 1;

            if (lane_act) {
                const u64 ba = (R == 8) ? ra[7] : ra[6]; // constant-index select!
                const u64 bb = (R == 8) ? rb[7] : rb[6];
                *(ulonglong2*)&xbuf[p][0][w][pl][0] = make_ulonglong2(ra[0], rb[0]);
                *(ulonglong2*)&xbuf[p][1][w][pl][0] = make_ulonglong2(ba, bb);
            }
            __syncthreads();

            u64 pa = 0, pb = 0, na = 0, nb = 0;
            if (lane_act && w > 0) {
                ulonglong2 v = *(ulonglong2*)&xbuf[p][1][w - 1][pl][0];
                pa = v.x; pb = v.y;
            }
            if (lane_act && w < NW - 1) {
                ulonglong2 v = *(ulonglong2*)&xbuf[p][0][w + 1][pl][0];
                na = v.x; nb = v.y;
            }

            #pragma unroll
            for (int i = 0; i < B_RMAX; i++) {
                if (i < R) {
                    const u64 ca = ra[i], cb = rb[i];
                    u64 xa = na, xb = nb;
                    if (i + 1 < B_RMAX) {
                        if (i + 1 < R) { xa = ra[i + 1]; xb = rb[i + 1]; }
                    }
                    const u64 lf = __shfl_up_sync(0xffffffffu, cb, 1);
                    const u64 rt = __shfl_down_sync(0xffffffffu, ca, 1);

                    u64 t, s0, s1;
                    ADD_F32X2(t, ca, cb);
                    ADD_F32X2(s0, t, lf);
                    ADD_F32X2(s0, s0, pa);
                    ADD_F32X2(s0, s0, xa);
                    ADD_F32X2(s1, t, rt);
                    ADD_F32X2(s1, s1, pb);
                    ADD_F32X2(s1, s1, xb);

                    float a0, a1, b0, b1;
                    UNPACK2(a0, a1, s0);
                    UNPACK2(b0, b1, s1);
                    a0 = fminf(a0, 1.0f); a1 = fminf(a1, 1.0f);
                    b0 = fminf(b0, 1.0f); b1 = fminf(b1, 1.0f);

                    if (!interior) {
                        const bool rin = (unsigned)(y0 + r_lo + i) < H_IMG;
                        const bool in  = rin && col_in;
                        a0 = in ? a0 : 0.0f;  a1 = in ? a1 : 0.0f;
                        b0 = in ? b0 : 0.0f;  b1 = in ? b1 : 0.0f;
                    }

                    pa = ca; pb = cb;
                    PACK2(ra[i], a0, a1);
                    PACK2(rb[i], b0, b1);
                }
            }
        }

        // Full BCE (inner cols local [6,54) <=> lanes 3..26; rows [5,53))
        float lsum = 0.0f;
        if (pl >= 3 && pl <= 26) {
            const float* tb = target + img;
            #pragma unroll
            for (int i = 0; i < B_RMAX; i++) {
                if (i < R) {
                    const int rl = r_lo + i;
                    if (rl >= B_HALO_Y && rl < B_HALO_Y + TILE) {
                        const float2 t2 = *(const float2*)(tb + (y0 + rl) * W_IMG + gx);
                        float h0, o0, h1, o1;
                        UNPACK2(h0, o0, ra[i]);
                        UNPACK2(h1, o1, rb[i]);
                        const float p0 = h0 * o0;
                        const float p1 = h1 * o1;
                        float c0, c1;
                        if (p0 >= 1.0f) c0 = -100.0f * (1.0f - t2.x);
                        else {
                            float lp  = fmaxf(logf(p0), -100.0f);
                            float l1p = fmaxf(logf(1.0f - p0), -100.0f);
                            c0 = t2.x * lp + (1.0f - t2.x) * l1p;
                        }
                        if (p1 >= 1.0f) c1 = -100.0f * (1.0f - t2.y);
                        else {
                            float lp  = fmaxf(logf(p1), -100.0f);
                            float l1p = fmaxf(logf(1.0f - p1), -100.0f);
                            c1 = t2.y * lp + (1.0f - t2.y) * l1p;
                        }
                        lsum += c0 + c1;
                    }
                }
            }
        }

        #pragma unroll
        for (int off = 16; off > 0; off >>= 1)
            lsum += __shfl_down_sync(0xffffffffu, lsum, off);

        if (pl == 0) red[w] = lsum;
        __syncthreads();

        if (tid < NW) {
            float v = red[tid];
            #pragma unroll
            for (int off = NW / 2; off > 0; off >>= 1)
                v += __shfl_down_sync((1u << NW) - 1u, v, off);
            if (tid == 0) atomicAdd(&g_accum, v);
        }
        __syncthreads();    // xbuf/red reuse safety across queue entries
    }

    // ---- Completion among FB_GRID blocks; last one finalizes + resets ----
    if (tid == 0) {
        __threadfence();
        const int t = atomicAdd(&g_done, 1);
        if (t == gridDim.x - 1) {
            __threadfence();
            const float a = *((volatile float*)&g_accum);
            const float inv_total = 1.0f / ((float)N_IMG * H_IMG * W_IMG);
            *out = -a * inv_total;
            g_accum = 0.0f;      // clean state for the next graph replay
            g_nfail = 0;
            g_done  = 0;
            __threadfence();
        }
    }
}

extern "C" void kernel_launch(void* const* d_in, const int* in_sizes, int n_in,
                              void* d_out, int out_size)
{
    const float* hand   = (const float*)d_in[0];
    const float* obj    = (const float*)d_in[1];
    const float* target = (const float*)d_in[2];
    float* out = (float*)d_out;

    dim3 grid(W_IMG / TILE, H_IMG / TILE, N_IMG);    // 8 x 8 x 64 = 4096 blocks
    bce_fast_kernel<<<grid, NTHREADS>>>(hand, obj, target);
    bce_fallback_kernel<<<FB_GRID, NTHREADS>>>(hand, obj, target, out);
}

// round 12
// speedup vs baseline: 1.4148x; 1.2143x over previous
#include <cuda_runtime.h>

// BoundaryBCELoss: 5x clamped plus-dilation of two masks + BCE vs target, mean-reduced.
// Round 12: (1) fast kernel lane utilization 26/32 -> 32/32: TILE_X=60, local 64 cols
// = exactly 32 column pairs, grid.x=7 with masked partial tile (col_in). Shfl-edge
// garbage (local cols 0/63) never reaches the inner region [2,62) within 2 iterations.
// (2) fallback grid 148 -> 16; each failed 60-wide tile processed as two 30-wide
// halves (21 pairs) since halo-5 over 60 cols would exceed 32 pairs. Rare path.
// Kept: halo-2 register tile, bitwise-1 certificate, target L2 prefetch, queue,
// small-grid completion counter + finalizer.

#define W_IMG 384
#define H_IMG 384
#define N_IMG 64
#define TILE_X 60
#define TILE_Y 48
#define GRID_X 7             // ceil(384/60)
#define GRID_Y 8
#define NBLK (GRID_X * GRID_Y * N_IMG)   // 3584

// ---- fast kernel (A): halo 2 ----
#define A_HALO 2
#define A_LX 64              // TILE_X + 4
#define A_LY 52              // TILE_Y + 4
#define A_RMAX 7             // warps 0-3: 7 rows, warps 4-7: 6 rows

// ---- fallback (B): halo 5 (x-halo 6, 8B alignment), per 30-col half-tile ----
#define B_HALF 30
#define B_HX 6
#define B_HY 5
#define B_LX 42              // 30 + 12
#define B_LY 58              // 48 + 10
#define B_NP 21              // column pairs
#define B_RMAX 8             // warps 0,1: 8 rows, warps 2-7: 7 rows

#define NW 8
#define NTHREADS 256
#define FB_GRID 16

typedef unsigned long long u64;
#define ONE2 0x3F8000003F800000ULL

#define ADD_F32X2(o, a, b) \
    asm("add.rn.f32x2 %0, %1, %2;" : "=l"(o) : "l"(a), "l"(b))
#define PACK2(o, lo, hi) \
    asm("mov.b64 %0, {%1, %2};" : "=l"(o) : "f"(lo), "f"(hi))
#define UNPACK2(lo, hi, in) \
    asm("mov.b64 {%0, %1}, %2;" : "=f"(lo), "=f"(hi) : "l"(in))

__device__ int   g_list[NBLK];       // failed-bid queue
__device__ int   g_nfail = 0;        // queue length; reset by finalizer
__device__ float g_accum = 0.0f;     // loss accumulator; reset by finalizer
__device__ int   g_done  = 0;        // completion counter; reset by finalizer

// ============================ Kernel A: fast path ============================
__global__ __launch_bounds__(NTHREADS) void bce_fast_kernel(
    const float* __restrict__ hand,
    const float* __restrict__ obj,
    const float* __restrict__ target)
{
    __shared__ __align__(16) u64 xbuf[2][2][NW][32][2];
    __shared__ float red[NW];

    const int n   = blockIdx.z;
    const int y0  = blockIdx.y * TILE_Y - A_HALO;
    const int x0  = blockIdx.x * TILE_X - A_HALO;        // even
    const int tid = threadIdx.x;
    const int w   = tid >> 5;
    const int pl  = tid & 31;
    const int bid = (blockIdx.z * GRID_Y + blockIdx.y) * GRID_X + blockIdx.x;

    // Row bands over 52 rows: warps 0-3 -> 7 rows; warps 4-7 -> 6 rows.
    const int r_lo = (w < 4) ? 7 * w : 6 * w + 4;
    const int R    = (w < 4) ? 7 : 6;

    const int  gx     = x0 + 2 * pl;                      // pair {gx, gx+1} in or out
    const bool col_in = ((unsigned)gx < W_IMG);           // x0 even => pair-uniform
    const bool interior = (x0 >= 0) && (y0 >= 0) &&
                          (x0 + A_LX <= W_IMG) && (y0 + A_LY <= H_IMG);

    const size_t img = (size_t)n * H_IMG * W_IMG;
    const float* hb = hand + img;
    const float* ob = obj + img;
    const float* tb = target + img;

    // ---- Stage band rows into registers; prefetch target rows to L2 ----
    u64 ra[A_RMAX], rb[A_RMAX];
    #pragma unroll
    for (int i = 0; i < A_RMAX; i++) { ra[i] = 0; rb[i] = 0; }

    #pragma unroll
    for (int i = 0; i < A_RMAX; i++) {
        if (i < R) {
            const int rl = r_lo + i;
            const int gy = y0 + rl;
            if (col_in && (unsigned)gy < H_IMG) {
                const float2 hh = *(const float2*)(hb + gy * W_IMG + gx);
                const float2 oo = *(const float2*)(ob + gy * W_IMG + gx);
                PACK2(ra[i], hh.x, oo.x);
                PACK2(rb[i], hh.y, oo.y);
            }
            // Warm L2 with the target row this warp reads post-certificate.
            if (((pl & 15) == 1) && rl >= A_HALO && rl < A_HALO + TILE_Y && col_in)
                asm volatile("prefetch.global.L2 [%0];"
                             :: "l"(tb + (y0 + rl) * W_IMG + gx));
        }
    }

    // ---- 2 dilation iterations (halo-2 => inner [2,62)x[2,50) is EXACT h2/o2;
    //      shfl-edge garbage at local cols 0/63 propagates <= 1 col inward) ----
    #pragma unroll
    for (int k = 0; k < 2; k++) {
        const int p = k;

        {
            const u64 ba = (R == 7) ? ra[6] : ra[5];   // constant-index select!
            const u64 bb = (R == 7) ? rb[6] : rb[5];
            *(ulonglong2*)&xbuf[p][0][w][pl][0] = make_ulonglong2(ra[0], rb[0]);
            *(ulonglong2*)&xbuf[p][1][w][pl][0] = make_ulonglong2(ba, bb);
        }
        __syncthreads();

        u64 pa = 0, pb = 0, na = 0, nb = 0;
        if (w > 0) {
            ulonglong2 v = *(ulonglong2*)&xbuf[p][1][w - 1][pl][0];
            pa = v.x; pb = v.y;
        }
        if (w < NW - 1) {
            ulonglong2 v = *(ulonglong2*)&xbuf[p][0][w + 1][pl][0];
            na = v.x; nb = v.y;
        }

        #pragma unroll
        for (int i = 0; i < A_RMAX; i++) {
            if (i < R) {
                const u64 ca = ra[i], cb = rb[i];
                u64 xa = na, xb = nb;
                if (i + 1 < A_RMAX) {
                    if (i + 1 < R) { xa = ra[i + 1]; xb = rb[i + 1]; }
                }
                const u64 lf = __shfl_up_sync(0xffffffffu, cb, 1);   // col 2pl-1
                const u64 rt = __shfl_down_sync(0xffffffffu, ca, 1); // col 2pl+2

                u64 t, s0, s1;
                ADD_F32X2(t, ca, cb);
                ADD_F32X2(s0, t, lf);
                ADD_F32X2(s0, s0, pa);
                ADD_F32X2(s0, s0, xa);
                ADD_F32X2(s1, t, rt);
                ADD_F32X2(s1, s1, pb);
                ADD_F32X2(s1, s1, xb);

                float a0, a1, b0, b1;
                UNPACK2(a0, a1, s0);
                UNPACK2(b0, b1, s1);
                a0 = fminf(a0, 1.0f); a1 = fminf(a1, 1.0f);
                b0 = fminf(b0, 1.0f); b1 = fminf(b1, 1.0f);

                if (!interior) {
                    // Re-zero out-of-image cells: reference zero-pads EVERY conv.
                    const bool rin = (unsigned)(y0 + r_lo + i) < H_IMG;
                    const bool in  = rin && col_in;
                    a0 = in ? a0 : 0.0f;  a1 = in ? a1 : 0.0f;
                    b0 = in ? b0 : 0.0f;  b1 = in ? b1 : 0.0f;
                }

                pa = ca; pb = cb;
                PACK2(ra[i], a0, a1);
                PACK2(rb[i], b0, b1);
            }
        }
    }

    // ---- Certificate: all IN-IMAGE inner-tile cells bitwise {1,1} => h5=o5=1
    //      there (monotone: in-image cell==1 stays 1; out-of-image stay 0) ----
    bool ok = true;
    if (pl >= 1 && pl <= 30 && col_in) {         // inner cols local [2,62)
        #pragma unroll
        for (int i = 0; i < A_RMAX; i++) {
            if (i < R) {
                const int rl = r_lo + i;
                if (rl >= A_HALO && rl < A_HALO + TILE_Y)   // rows always in-image
                    ok = ok && (ra[i] == ONE2) && (rb[i] == ONE2);
            }
        }
    }
    const bool pass = __syncthreads_and(ok);

    if (!pass) {
        if (tid == 0) {
            const int pos = atomicAdd(&g_nfail, 1);
            g_list[pos] = bid;                   // fallback kernel handles this tile
        }
        return;
    }

    // ---- BCE with p==1 everywhere: contrib = -100*(1-t)  (target in L2) ----
    float ts = 0.0f;
    int cells = 0;
    if (pl >= 1 && pl <= 30 && col_in) {
        #pragma unroll
        for (int i = 0; i < A_RMAX; i++) {
            if (i < R) {
                const int rl = r_lo + i;
                if (rl >= A_HALO && rl < A_HALO + TILE_Y) {
                    const float2 t2 = *(const float2*)(tb + (y0 + rl) * W_IMG + gx);
                    ts += t2.x + t2.y;
                    cells += 2;
                }
            }
        }
    }
    float lsum = -100.0f * ((float)cells - ts);

    #pragma unroll
    for (int off = 16; off > 0; off >>= 1)
        lsum += __shfl_down_sync(0xffffffffu, lsum, off);

    if (pl == 0) red[w] = lsum;
    __syncthreads();

    if (tid < NW) {
        float v = red[tid];
        #pragma unroll
        for (int off = NW / 2; off > 0; off >>= 1)
            v += __shfl_down_sync((1u << NW) - 1u, v, off);
        if (tid == 0) atomicAdd(&g_accum, v);
    }
}

// ====== Kernel B: queue-driven fallback (two 30-col halves per failed tile) ======
__global__ __launch_bounds__(NTHREADS) void bce_fallback_kernel(
    const float* __restrict__ hand,
    const float* __restrict__ obj,
    const float* __restrict__ target,
    float* __restrict__ out)
{
    __shared__ __align__(16) u64 xbuf[2][2][NW][B_NP][2];
    __shared__ float red[NW];
    __shared__ int s_nfail;

    const int tid = threadIdx.x;
    const int w   = tid >> 5;
    const int pl  = tid & 31;

    if (tid == 0) s_nfail = *((volatile int*)&g_nfail);
    __syncthreads();
    const int nunits = 2 * s_nfail;              // block-uniform

    for (int u = blockIdx.x; u < nunits; u += gridDim.x) {
        const int q   = u >> 1;
        const int hh_ = u & 1;                   // which 30-col half
        const int bid = g_list[q];
        const int bx  = bid % GRID_X;
        const int by  = (bid / GRID_X) % GRID_Y;
        const int n   = bid / (GRID_X * GRID_Y);

        const int y0 = by * TILE_Y - B_HY;
        const int x0 = bx * TILE_X + hh_ * B_HALF - B_HX;   // even

        const int r_lo = 7 * w + (w < 2 ? w : 2);
        const int R    = (w < 2) ? 8 : 7;

        const int  gx       = x0 + 2 * pl;
        const bool lane_act = (pl < B_NP);
        const bool col_in   = lane_act && ((unsigned)gx < W_IMG);
        const bool interior = (x0 >= 0) && (y0 >= 0) &&
                              (x0 + B_LX <= W_IMG) && (y0 + B_LY <= H_IMG);

        const size_t img = (size_t)n * H_IMG * W_IMG;
        const float* hb = hand + img;
        const float* ob = obj + img;

        u64 ra[B_RMAX], rb[B_RMAX];
        #pragma unroll
        for (int i = 0; i < B_RMAX; i++) { ra[i] = 0; rb[i] = 0; }

        #pragma unroll
        for (int i = 0; i < B_RMAX; i++) {
            if (i < R) {
                const int gy = y0 + r_lo + i;
                if (col_in && (unsigned)gy < H_IMG) {
                    const float2 hh = *(const float2*)(hb + gy * W_IMG + gx);
                    const float2 oo = *(const float2*)(ob + gy * W_IMG + gx);
                    PACK2(ra[i], hh.x, oo.x);
                    PACK2(rb[i], hh.y, oo.y);
                }
            }
        }

        #pragma unroll 1
        for (int k = 0; k < 5; k++) {
            const int p = k & 1;

            if (lane_act) {
                const u64 ba = (R == 8) ? ra[7] : ra[6]; // constant-index select!
                const u64 bb = (R == 8) ? rb[7] : rb[6];
                *(ulonglong2*)&xbuf[p][0][w][pl][0] = make_ulonglong2(ra[0], rb[0]);
                *(ulonglong2*)&xbuf[p][1][w][pl][0] = make_ulonglong2(ba, bb);
            }
            __syncthreads();

            u64 pa = 0, pb = 0, na = 0, nb = 0;
            if (lane_act && w > 0) {
                ulonglong2 v = *(ulonglong2*)&xbuf[p][1][w - 1][pl][0];
                pa = v.x; pb = v.y;
            }
            if (lane_act && w < NW - 1) {
                ulonglong2 v = *(ulonglong2*)&xbuf[p][0][w + 1][pl][0];
                na = v.x; nb = v.y;
            }

            #pragma unroll
            for (int i = 0; i < B_RMAX; i++) {
                if (i < R) {
                    const u64 ca = ra[i], cb = rb[i];
                    u64 xa = na, xb = nb;
                    if (i + 1 < B_RMAX) {
                        if (i + 1 < R) { xa = ra[i + 1]; xb = rb[i + 1]; }
                    }
                    const u64 lf = __shfl_up_sync(0xffffffffu, cb, 1);
                    const u64 rt = __shfl_down_sync(0xffffffffu, ca, 1);

                    u64 t, s0, s1;
                    ADD_F32X2(t, ca, cb);
                    ADD_F32X2(s0, t, lf);
                    ADD_F32X2(s0, s0, pa);
                    ADD_F32X2(s0, s0, xa);
                    ADD_F32X2(s1, t, rt);
                    ADD_F32X2(s1, s1, pb);
                    ADD_F32X2(s1, s1, xb);

                    float a0, a1, b0, b1;
                    UNPACK2(a0, a1, s0);
                    UNPACK2(b0, b1, s1);
                    a0 = fminf(a0, 1.0f); a1 = fminf(a1, 1.0f);
                    b0 = fminf(b0, 1.0f); b1 = fminf(b1, 1.0f);

                    if (!interior) {
                        const bool rin = (unsigned)(y0 + r_lo + i) < H_IMG;
                        const bool in  = rin && col_in;
                        a0 = in ? a0 : 0.0f;  a1 = in ? a1 : 0.0f;
                        b0 = in ? b0 : 0.0f;  b1 = in ? b1 : 0.0f;
                    }

                    pa = ca; pb = cb;
                    PACK2(ra[i], a0, a1);
                    PACK2(rb[i], b0, b1);
                }
            }
        }

        // Full BCE over this half's inner region: cols local [6,36) <=> lanes
        // 3..17, rows local [5,53), in-image columns only.
        float lsum = 0.0f;
        if (pl >= 3 && pl <= 17 && col_in) {
            const float* tb = target + img;
            #pragma unroll
            for (int i = 0; i < B_RMAX; i++) {
                if (i < R) {
                    const int rl = r_lo + i;
                    if (rl >= B_HY && rl < B_HY + TILE_Y) {
                        const float2 t2 = *(const float2*)(tb + (y0 + rl) * W_IMG + gx);
                        float h0, o0, h1, o1;
                        UNPACK2(h0, o0, ra[i]);
                        UNPACK2(h1, o1, rb[i]);
                        const float p0 = h0 * o0;
                        const float p1 = h1 * o1;
                        float c0, c1;
                        if (p0 >= 1.0f) c0 = -100.0f * (1.0f - t2.x);
                        else {
                            float lp  = fmaxf(logf(p0), -100.0f);
                            float l1p = fmaxf(logf(1.0f - p0), -100.0f);
                            c0 = t2.x * lp + (1.0f - t2.x) * l1p;
                        }
                        if (p1 >= 1.0f) c1 = -100.0f * (1.0f - t2.y);
                        else {
                            float lp  = fmaxf(logf(p1), -100.0f);
                            float l1p = fmaxf(logf(1.0f - p1), -100.0f);
                            c1 = t2.y * lp + (1.0f - t2.y) * l1p;
                        }
                        lsum += c0 + c1;
                    }
                }
            }
        }

        #pragma unroll
        for (int off = 16; off > 0; off >>= 1)
            lsum += __shfl_down_sync(0xffffffffu, lsum, off);

        if (pl == 0) red[w] = lsum;
        __syncthreads();

        if (tid < NW) {
            float v = red[tid];
            #pragma unroll
            for (int off = NW / 2; off > 0; off >>= 1)
                v += __shfl_down_sync((1u << NW) - 1u, v, off);
            if (tid == 0) atomicAdd(&g_accum, v);
        }
        __syncthreads();    // xbuf/red reuse safety across queue units
    }

    // ---- Completion among FB_GRID blocks; last one finalizes + resets ----
    if (tid == 0) {
        __threadfence();
        const int t = atomicAdd(&g_done, 1);
        if (t == gridDim.x - 1) {
            __threadfence();
            const float a = *((volatile float*)&g_accum);
            const float inv_total = 1.0f / ((float)N_IMG * H_IMG * W_IMG);
            *out = -a * inv_total;
            g_accum = 0.0f;      // clean state for the next graph replay
            g_nfail = 0;
            g_done  = 0;
            __threadfence();
        }
    }
}

extern "C" void kernel_launch(void* const* d_in, const int* in_sizes, int n_in,
                              void* d_out, int out_size)
{
    const float* hand   = (const float*)d_in[0];
    const float* obj    = (const float*)d_in[1];
    const float* target = (const float*)d_in[2];
    float* out = (float*)d_out;

    dim3 grid(GRID_X, GRID_Y, N_IMG);    // 7 x 8 x 64 = 3584 blocks
    bce_fast_kernel<<<grid, NTHREADS>>>(hand, obj, target);
    bce_fallback_kernel<<<FB_GRID, NTHREADS>>>(hand, obj, target, out);
}

// round 13
// speedup vs baseline: 1.5788x; 1.1159x over previous
#include <cuda_runtime.h>

// BoundaryBCELoss: 5x clamped plus-dilation of two masks + BCE vs target, mean-reduced.
// Round 13: (1) PDL -- fallback kernel launched with programmatic stream serialization
// and cudaGridDependencySynchronize() so its ~6us launch gap overlaps the fast kernel
// (guarded: plain launch if the attribute is rejected). (2) uniform row bands in the
// fast kernel: TILE_Y=44 -> 48 local rows = 6/warp exactly; all row-count predicates
// and publishes become compile-time. (3) packed f32x2 BCE target accumulation.
// Kept: TILE_X=60 (32 full column pairs), halo-2 register tile, bitwise-1 certificate,
// target L2 prefetch, failure queue, small-grid finalizer.

#define W_IMG 384
#define H_IMG 384
#define N_IMG 64
#define TILE_X 60
#define TILE_Y 44
#define GRID_X 7             // ceil(384/60)
#define GRID_Y 9             // ceil(384/44)
#define NBLK (GRID_X * GRID_Y * N_IMG)   // 4032

// ---- fast kernel (A): halo 2, uniform bands ----
#define A_HALO 2
#define A_LX 64              // TILE_X + 4 (exactly 32 column pairs)
#define A_LY 48              // TILE_Y + 4 (exactly 6 rows per warp)
#define A_R 6

// ---- fallback (B): halo 5 (x-halo 6, 8B alignment), per 30-col half-tile ----
#define B_HALF 30
#define B_HX 6
#define B_HY 5
#define B_LX 42              // 30 + 12
#define B_LY 54              // 44 + 10
#define B_NP 21              // column pairs
#define B_RMAX 7             // warps 0-5: 7 rows, warps 6,7: 6 rows

#define NW 8
#define NTHREADS 256
#define FB_GRID 8

typedef unsigned long long u64;
#define ONE2 0x3F8000003F800000ULL

#define ADD_F32X2(o, a, b) \
    asm("add.rn.f32x2 %0, %1, %2;" : "=l"(o) : "l"(a), "l"(b))
#define PACK2(o, lo, hi) \
    asm("mov.b64 %0, {%1, %2};" : "=l"(o) : "f"(lo), "f"(hi))
#define UNPACK2(lo, hi, in) \
    asm("mov.b64 {%0, %1}, %2;" : "=f"(lo), "=f"(hi) : "l"(in))

__device__ int   g_list[NBLK];       // failed-bid queue
__device__ int   g_nfail = 0;        // queue length; reset by finalizer
__device__ float g_accum = 0.0f;     // loss accumulator; reset by finalizer
__device__ int   g_done  = 0;        // completion counter; reset by finalizer

// ============================ Kernel A: fast path ============================
__global__ __launch_bounds__(NTHREADS) void bce_fast_kernel(
    const float* __restrict__ hand,
    const float* __restrict__ obj,
    const float* __restrict__ target)
{
    __shared__ __align__(16) u64 xbuf[2][2][NW][32][2];
    __shared__ float red[NW];

    const int n   = blockIdx.z;
    const int y0  = blockIdx.y * TILE_Y - A_HALO;
    const int x0  = blockIdx.x * TILE_X - A_HALO;        // even
    const int tid = threadIdx.x;
    const int w   = tid >> 5;
    const int pl  = tid & 31;
    const int bid = (blockIdx.z * GRID_Y + blockIdx.y) * GRID_X + blockIdx.x;

    const int r_lo = A_R * w;                             // uniform 6 rows/warp

    const int  gx     = x0 + 2 * pl;                      // pair {gx, gx+1} in or out
    const bool col_in = ((unsigned)gx < W_IMG);           // x0 even => pair-uniform
    const bool interior = (x0 >= 0) && (y0 >= 0) &&
                          (x0 + A_LX <= W_IMG) && (y0 + A_LY <= H_IMG);

    const size_t img = (size_t)n * H_IMG * W_IMG;
    const float* hb = hand + img;
    const float* ob = obj + img;
    const float* tb = target + img;

    // ---- Stage band rows into registers; prefetch target rows to L2 ----
    u64 ra[A_R], rb[A_R];
    #pragma unroll
    for (int i = 0; i < A_R; i++) { ra[i] = 0; rb[i] = 0; }

    #pragma unroll
    for (int i = 0; i < A_R; i++) {
        const int rl = r_lo + i;
        const int gy = y0 + rl;
        if (col_in && (unsigned)gy < H_IMG) {
            const float2 hh = *(const float2*)(hb + gy * W_IMG + gx);
            const float2 oo = *(const float2*)(ob + gy * W_IMG + gx);
            PACK2(ra[i], hh.x, oo.x);
            PACK2(rb[i], hh.y, oo.y);
        }
        // Warm L2 with the target row this warp reads post-certificate.
        if (((pl & 15) == 1) && rl >= A_HALO && rl < A_HALO + TILE_Y &&
            col_in && (unsigned)gy < H_IMG)
            asm volatile("prefetch.global.L2 [%0];"
                         :: "l"(tb + gy * W_IMG + gx));
    }

    // ---- 2 dilation iterations (halo-2 => inner [2,62)x[2,46) is EXACT h2/o2;
    //      shfl-edge garbage at local cols 0/63 propagates <= 1 col inward) ----
    #pragma unroll
    for (int k = 0; k < 2; k++) {
        const int p = k;

        *(ulonglong2*)&xbuf[p][0][w][pl][0] = make_ulonglong2(ra[0], rb[0]);
        *(ulonglong2*)&xbuf[p][1][w][pl][0] = make_ulonglong2(ra[A_R - 1], rb[A_R - 1]);
        __syncthreads();

        u64 pa = 0, pb = 0, na = 0, nb = 0;
        if (w > 0) {
            ulonglong2 v = *(ulonglong2*)&xbuf[p][1][w - 1][pl][0];
            pa = v.x; pb = v.y;
        }
        if (w < NW - 1) {
            ulonglong2 v = *(ulonglong2*)&xbuf[p][0][w + 1][pl][0];
            na = v.x; nb = v.y;
        }

        #pragma unroll
        for (int i = 0; i < A_R; i++) {
            const u64 ca = ra[i], cb = rb[i];
            const u64 xa = (i + 1 < A_R) ? ra[i + 1] : na;
            const u64 xb = (i + 1 < A_R) ? rb[i + 1] : nb;
            const u64 lf = __shfl_up_sync(0xffffffffu, cb, 1);   // col 2pl-1
            const u64 rt = __shfl_down_sync(0xffffffffu, ca, 1); // col 2pl+2

            u64 t, s0, s1;
            ADD_F32X2(t, ca, cb);
            ADD_F32X2(s0, t, lf);
            ADD_F32X2(s0, s0, pa);
            ADD_F32X2(s0, s0, xa);
            ADD_F32X2(s1, t, rt);
            ADD_F32X2(s1, s1, pb);
            ADD_F32X2(s1, s1, xb);

            float a0, a1, b0, b1;
            UNPACK2(a0, a1, s0);
            UNPACK2(b0, b1, s1);
            a0 = fminf(a0, 1.0f); a1 = fminf(a1, 1.0f);
            b0 = fminf(b0, 1.0f); b1 = fminf(b1, 1.0f);

            if (!interior) {
                // Re-zero out-of-image cells: reference zero-pads EVERY conv.
                const bool rin = (unsigned)(y0 + r_lo + i) < H_IMG;
                const bool in  = rin && col_in;
                a0 = in ? a0 : 0.0f;  a1 = in ? a1 : 0.0f;
                b0 = in ? b0 : 0.0f;  b1 = in ? b1 : 0.0f;
            }

            pa = ca; pb = cb;                    // old row becomes "up"
            PACK2(ra[i], a0, a1);
            PACK2(rb[i], b0, b1);
        }
    }

    // ---- Certificate: all IN-IMAGE inner-tile cells bitwise {1,1} => h5=o5=1
    //      there (monotone: in-image cell==1 stays 1; out-of-image stay 0) ----
    bool ok = true;
    if (pl >= 1 && pl <= 30 && col_in) {         // inner cols local [2,62)
        #pragma unroll
        for (int i = 0; i < A_R; i++) {
            const int rl = r_lo + i;
            if (rl >= A_HALO && rl < A_HALO + TILE_Y &&
                (unsigned)(y0 + rl) < H_IMG)     // in-image rows only
                ok = ok && (ra[i] == ONE2) && (rb[i] == ONE2);
        }
    }
    const bool pass = __syncthreads_and(ok);

    if (!pass) {
        if (tid == 0) {
            const int pos = atomicAdd(&g_nfail, 1);
            g_list[pos] = bid;                   // fallback kernel handles this tile
        }
        return;
    }

    // ---- BCE with p==1 everywhere: contrib = -100*(1-t)  (target in L2) ----
    u64 tacc = 0;
    int cells = 0;
    if (pl >= 1 && pl <= 30 && col_in) {
        #pragma unroll
        for (int i = 0; i < A_R; i++) {
            const int rl = r_lo + i;
            const int gy = y0 + rl;
            if (rl >= A_HALO && rl < A_HALO + TILE_Y && (unsigned)gy < H_IMG) {
                const u64 t2 = *(const u64*)(tb + gy * W_IMG + gx);
                ADD_F32X2(tacc, tacc, t2);
                cells += 2;
            }
        }
    }
    float tlo, thi;
    UNPACK2(tlo, thi, tacc);
    float lsum = -100.0f * ((float)cells - tlo - thi);

    #pragma unroll
    for (int off = 16; off > 0; off >>= 1)
        lsum += __shfl_down_sync(0xffffffffu, lsum, off);

    if (pl == 0) red[w] = lsum;
    __syncthreads();

    if (tid < NW) {
        float v = red[tid];
        #pragma unroll
        for (int off = NW / 2; off > 0; off >>= 1)
            v += __shfl_down_sync((1u << NW) - 1u, v, off);
        if (tid == 0) atomicAdd(&g_accum, v);
    }
}

// ====== Kernel B: queue-driven fallback (two 30-col halves per failed tile) ======
__global__ __launch_bounds__(NTHREADS) void bce_fallback_kernel(
    const float* __restrict__ hand,
    const float* __restrict__ obj,
    const float* __restrict__ target,
    float* __restrict__ out)
{
    // PDL: this kernel may start before bce_fast_kernel finishes. Wait for it
    // before reading the queue/accumulator. No-op when launched without PDL.
    cudaGridDependencySynchronize();

    __shared__ __align__(16) u64 xbuf[2][2][NW][B_NP][2];
    __shared__ float red[NW];
    __shared__ int s_nfail;

    const int tid = threadIdx.x;
    const int w   = tid >> 5;
    const int pl  = tid & 31;

    if (tid == 0) s_nfail = *((volatile int*)&g_nfail);
    __syncthreads();
    const int nunits = 2 * s_nfail;              // block-uniform

    for (int u = blockIdx.x; u < nunits; u += gridDim.x) {
        const int q   = u >> 1;
        const int hh_ = u & 1;                   // which 30-col half
        const int bid = g_list[q];
        const int bx  = bid % GRID_X;
        const int by  = (bid / GRID_X) % GRID_Y;
        const int n   = bid / (GRID_X * GRID_Y);

        const int y0 = by * TILE_Y - B_HY;
        const int x0 = bx * TILE_X + hh_ * B_HALF - B_HX;   // even

        // 54 rows over 8 warps: warps 0-5 -> 7 rows; warps 6,7 -> 6 rows.
        const int r_lo = (w < 6) ? 7 * w : 6 * w + 6;
        const int R    = (w < 6) ? 7 : 6;

        const int  gx       = x0 + 2 * pl;
        const bool lane_act = (pl < B_NP);
        const bool col_in   = lane_act && ((unsigned)gx < W_IMG);
        const bool interior = (x0 >= 0) && (y0 >= 0) &&
                              (x0 + B_LX <= W_IMG) && (y0 + B_LY <= H_IMG);

        const size_t img = (size_t)n * H_IMG * W_IMG;
        const float* hb = hand + img;
        const float* ob = obj + img;

        u64 ra[B_RMAX], rb[B_RMAX];
        #pragma unroll
        for (int i = 0; i < B_RMAX; i++) { ra[i] = 0; rb[i] = 0; }

        #pragma unroll
        for (int i = 0; i < B_RMAX; i++) {
            if (i < R) {
                const int gy = y0 + r_lo + i;
                if (col_in && (unsigned)gy < H_IMG) {
                    const float2 hh = *(const float2*)(hb + gy * W_IMG + gx);
                    const float2 oo = *(const float2*)(ob + gy * W_IMG + gx);
                    PACK2(ra[i], hh.x, oo.x);
                    PACK2(rb[i], hh.y, oo.y);
                }
            }
        }

        #pragma unroll 1
        for (int k = 0; k < 5; k++) {
            const int p = k & 1;

            if (lane_act) {
                const u64 ba = (R == 7) ? ra[6] : ra[5]; // constant-index select!
                const u64 bb = (R == 7) ? rb[6] : rb[5];
                *(ulonglong2*)&xbuf[p][0][w][pl][0] = make_ulonglong2(ra[0], rb[0]);
                *(ulonglong2*)&xbuf[p][1][w][pl][0] = make_ulonglong2(ba, bb);
            }
            __syncthreads();

            u64 pa = 0, pb = 0, na = 0, nb = 0;
            if (lane_act && w > 0) {
                ulonglong2 v = *(ulonglong2*)&xbuf[p][1][w - 1][pl][0];
                pa = v.x; pb = v.y;
            }
            if (lane_act && w < NW - 1) {
                ulonglong2 v = *(ulonglong2*)&xbuf[p][0][w + 1][pl][0];
                na = v.x; nb = v.y;
            }

            #pragma unroll
            for (int i = 0; i < B_RMAX; i++) {
                if (i < R) {
                    const u64 ca = ra[i], cb = rb[i];
                    u64 xa = na, xb = nb;
                    if (i + 1 < B_RMAX) {
                        if (i + 1 < R) { xa = ra[i + 1]; xb = rb[i + 1]; }
                    }
                    const u64 lf = __shfl_up_sync(0xffffffffu, cb, 1);
                    const u64 rt = __shfl_down_sync(0xffffffffu, ca, 1);

                    u64 t, s0, s1;
                    ADD_F32X2(t, ca, cb);
                    ADD_F32X2(s0, t, lf);
                    ADD_F32X2(s0, s0, pa);
                    ADD_F32X2(s0, s0, xa);
                    ADD_F32X2(s1, t, rt);
                    ADD_F32X2(s1, s1, pb);
                    ADD_F32X2(s1, s1, xb);

                    float a0, a1, b0, b1;
                    UNPACK2(a0, a1, s0);
                    UNPACK2(b0, b1, s1);
                    a0 = fminf(a0, 1.0f); a1 = fminf(a1, 1.0f);
                    b0 = fminf(b0, 1.0f); b1 = fminf(b1, 1.0f);

                    if (!interior) {
                        const bool rin = (unsigned)(y0 + r_lo + i) < H_IMG;
                        const bool in  = rin && col_in;
                        a0 = in ? a0 : 0.0f;  a1 = in ? a1 : 0.0f;
                        b0 = in ? b0 : 0.0f;  b1 = in ? b1 : 0.0f;
                    }

                    pa = ca; pb = cb;
                    PACK2(ra[i], a0, a1);
                    PACK2(rb[i], b0, b1);
                }
            }
        }

        // Full BCE over this half's inner region: cols local [6,36) <=> lanes
        // 3..17, rows local [5,49), in-image columns only.
        float lsum = 0.0f;
        if (pl >= 3 && pl <= 17 && col_in) {
            const float* tb = target + img;
            #pragma unroll
            for (int i = 0; i < B_RMAX; i++) {
                if (i < R) {
                    const int rl = r_lo + i;
                    const int gy = y0 + rl;
                    if (rl >= B_HY && rl < B_HY + TILE_Y && (unsigned)gy < H_IMG) {
                        const float2 t2 = *(const float2*)(tb + gy * W_IMG + gx);
                        float h0, o0, h1, o1;
                        UNPACK2(h0, o0, ra[i]);
                        UNPACK2(h1, o1, rb[i]);
                        const float p0 = h0 * o0;
                        const float p1 = h1 * o1;
                        float c0, c1;
                        if (p0 >= 1.0f) c0 = -100.0f * (1.0f - t2.x);
                        else {
                            float lp  = fmaxf(logf(p0), -100.0f);
                            float l1p = fmaxf(logf(1.0f - p0), -100.0f);
                            c0 = t2.x * lp + (1.0f - t2.x) * l1p;
                        }
                        if (p1 >= 1.0f) c1 = -100.0f * (1.0f - t2.y);
                        else {
                            float lp  = fmaxf(logf(p1), -100.0f);
                            float l1p = fmaxf(logf(1.0f - p1), -100.0f);
                            c1 = t2.y * lp + (1.0f - t2.y) * l1p;
                        }
                        lsum += c0 + c1;
                    }
                }
            }
        }

        #pragma unroll
        for (int off = 16; off > 0; off >>= 1)
            lsum += __shfl_down_sync(0xffffffffu, lsum, off);

        if (pl == 0) red[w] = lsum;
        __syncthreads();

        if (tid < NW) {
            float v = red[tid];
            #pragma unroll
            for (int off = NW / 2; off > 0; off >>= 1)
                v += __shfl_down_sync((1u << NW) - 1u, v, off);
            if (tid == 0) atomicAdd(&g_accum, v);
        }
        __syncthreads();    // xbuf/red reuse safety across queue units
    }

    // ---- Completion among FB_GRID blocks; last one finalizes + resets ----
    if (tid == 0) {
        __threadfence();
        const int t = atomicAdd(&g_done, 1);
        if (t == gridDim.x - 1) {
            __threadfence();
            const float a = *((volatile float*)&g_accum);
            const float inv_total = 1.0f / ((float)N_IMG * H_IMG * W_IMG);
            *out = -a * inv_total;
            g_accum = 0.0f;      // clean state for the next graph replay
            g_nfail = 0;
            g_done  = 0;
            __threadfence();
        }
    }
}

extern "C" void kernel_launch(void* const* d_in, const int* in_sizes, int n_in,
                              void* d_out, int out_size)
{
    const float* hand   = (const float*)d_in[0];
    const float* obj    = (const float*)d_in[1];
    const float* target = (const float*)d_in[2];
    float* out = (float*)d_out;

    dim3 grid(GRID_X, GRID_Y, N_IMG);    // 7 x 9 x 64 = 4032 blocks
    bce_fast_kernel<<<grid, NTHREADS>>>(hand, obj, target);

    // Fallback with programmatic dependent launch (pre-launch overlaps the fast
    // kernel; device-side cudaGridDependencySynchronize orders the data).
    cudaLaunchConfig_t cfg = {};
    cfg.gridDim  = dim3(FB_GRID, 1, 1);
    cfg.blockDim = dim3(NTHREADS, 1, 1);
    cudaLaunchAttribute attrs[1];
    attrs[0].id = cudaLaunchAttributeProgrammaticStreamSerialization;
    attrs[0].val.programmaticStreamSerializationAllowed = 1;
    cfg.attrs = attrs;
    cfg.numAttrs = 1;
    if (cudaLaunchKernelEx(&cfg, bce_fallback_kernel,
                           hand, obj, target, out) != cudaSuccess) {
        bce_fallback_kernel<<<FB_GRID, NTHREADS>>>(hand, obj, target, out);
    }
}